// round 2
// baseline (speedup 1.0000x reference)
#include <cuda_runtime.h>
#include <cuda_bf16.h>

// out[b, i*64 + j] = x[b, i] * W[i, j]
// B=8192, L=100, E=64. Output row = 6400 floats = 1600 float4.
// grid = (5, 8192), block = 320  ->  5*320 = 1600 float4 per batch row, exact.

#define L_DIM   100
#define E_DIM   64
#define ROW_F4  1600      // 6400 floats / 4

__global__ __launch_bounds__(320, 6)
void chem_embed_kernel(const float* __restrict__ x,
                       const float* __restrict__ W,
                       float* __restrict__ out)
{
    const int b = blockIdx.y;
    const int r = blockIdx.x * 320 + threadIdx.x;   // float4 index within row, [0,1600)

    const int i  = r >> 4;          // which of the 100 positions (16 float4 per position)
    // j4 = r & 15 is implicit in W indexing below.

    const float xv = __ldg(&x[b * L_DIM + i]);

    const float4 w4 = __ldg(&((const float4*)W)[r]);  // W is [100,64] = 1600 float4, row r maps 1:1

    float4 o;
    o.x = xv * w4.x;
    o.y = xv * w4.y;
    o.z = xv * w4.z;
    o.w = xv * w4.w;

    ((float4*)out)[(long long)b * ROW_F4 + r] = o;
}

extern "C" void kernel_launch(void* const* d_in, const int* in_sizes, int n_in,
                              void* d_out, int out_size)
{
    const float* x = (const float*)d_in[0];   // [8192, 100]
    const float* W = (const float*)d_in[1];   // [100, 64]
    float* out = (float*)d_out;               // [8192, 1, 6400]

    dim3 grid(5, 8192);
    dim3 block(320);
    chem_embed_kernel<<<grid, block>>>(x, W, out);
}